// round 4
// baseline (speedup 1.0000x reference)
#include <cuda_runtime.h>
#include <cstddef>

// ---------------------------------------------------------------------------
// bPC_SNN: 16-step predictive-coding SNN recurrence.
// B=128, d0=2048, d1=d2=4096, d3=512. Output = final ed3 [128,512] f32.
// ---------------------------------------------------------------------------

#define BATCH 128
#define DD0   2048
#define DD1   4096
#define DD3   512

static constexpr size_t S1 = (size_t)BATCH * DD1;   // 524288
static constexpr size_t S0 = (size_t)BATCH * DD0;   // 262144
static constexpr size_t S3 = (size_t)BATCH * DD3;   // 65536

// pool layout (floats). Zero-initialized prefix first.
static constexpr size_t OFF_V1  = 0;
static constexpr size_t OFF_TR1 = 1 * S1;
static constexpr size_t OFF_J1  = 2 * S1;
static constexpr size_t OFF_R1  = 3 * S1;
static constexpr size_t OFF_SP1 = 4 * S1;
static constexpr size_t OFF_V2  = 5 * S1;
static constexpr size_t OFF_TR2 = 6 * S1;
static constexpr size_t OFF_J2  = 7 * S1;
static constexpr size_t OFF_R2  = 8 * S1;
static constexpr size_t OFF_SP2 = 9 * S1;
static constexpr size_t OFF_EG1 = 10 * S1;
static constexpr size_t OFF_ED1 = 11 * S1;
static constexpr size_t OFF_ED2 = 12 * S1;
static constexpr size_t OFF_EG2 = 13 * S1;
static constexpr size_t OFF_EG0 = 14 * S1;
static constexpr size_t OFF_ZD  = 14 * S1 + S0;
static constexpr size_t OFF_ED3 = 14 * S1 + 2 * S0;
static constexpr size_t OFF_ZL  = 14 * S1 + 2 * S0 + S3;
static constexpr size_t ZERO_FLOATS = 14 * S1 + 2 * S0 + 2 * S3;
// scratch (fully overwritten each step; no zeroing needed)
static constexpr size_t OFF_TI1 = ZERO_FLOATS;            // 4 parts of [B,D1]
static constexpr size_t OFF_TI2 = OFF_TI1 + 4 * S1;       // 4 parts of [B,D1]
static constexpr size_t OFF_G2  = OFF_TI2 + 4 * S1;       // 2 parts (s2@W1^T)
static constexpr size_t OFF_G3  = OFF_G2 + 2 * S1;        // 2 parts (s1@V1^T)
static constexpr size_t OFF_C0  = OFF_G3 + 2 * S1;        // x@V0^T (const)
static constexpr size_t OFF_C1  = OFF_C0 + S1;            // y@W2^T (const)
static constexpr size_t OFF_G1  = OFF_C1 + S1;            // 4 parts of [B,D0]
static constexpr size_t OFF_G4  = OFF_G1 + 4 * S0;        // 16 parts of [B,D3]
static constexpr size_t POOL_FLOATS = OFF_G4 + 16 * S3;   // ~69.7 MB

__device__ float g_pool[POOL_FLOATS];

// ---------------------------------------------------------------------------
// Generic M=128 GEMM, partial-K output (deterministic split-K).
//   C_part[by][b][n] = sum_{k in chunk(by)} A[b][k] * Bop[k][n]
//   NN: Bop[k][n] = Bm[k*ldb + n]      (ldb = row stride of B)
//   NT: Bop[k][n] = Bm[n*ldb + k]      (ldb = row stride of B)
// Tile: BM=128, BN=64, BK=16. 256 threads, 8x4 microtile, reg prefetch.
// Requires: N % 64 == 0, kchunk % 16 == 0, lda % 4 == 0, ldb % 4 == 0.
// ---------------------------------------------------------------------------
template <bool TB>
__global__ __launch_bounds__(256)
void gemm128(const float* __restrict__ A, int lda,
             const float* __restrict__ Bm, int ldb,
             float* __restrict__ C, int N, int kchunk)
{
    __shared__ float As[16][128];
    __shared__ float Bs[16][68];   // 64 + pad

    const int tid = threadIdx.x;
    const int n0  = blockIdx.x * 64;
    const int k0  = blockIdx.y * kchunk;
    C += (size_t)blockIdx.y * 128 * N;

    // microtile mapping: 16 m-groups x 16 n-groups
    const int my8 = (tid >> 4) * 8;   // m offset (0..120)
    const int nx4 = (tid & 15) * 4;   // n offset (0..60)

    // A-load mapping: m = tid&127, k-half = tid>>7 (8 k each)
    const int am = tid & 127;
    const int ak = (tid >> 7) * 8;

    float acc[8][4];
#pragma unroll
    for (int i = 0; i < 8; ++i)
#pragma unroll
        for (int j = 0; j < 4; ++j) acc[i][j] = 0.0f;

    float4 pa[2];
    float4 pb;

    // prefetch tile 0
    {
        const float* ap = A + (size_t)am * lda + k0 + ak;
        pa[0] = *reinterpret_cast<const float4*>(ap);
        pa[1] = *reinterpret_cast<const float4*>(ap + 4);
        if (!TB) {
            pb = *reinterpret_cast<const float4*>(
                Bm + (size_t)(k0 + (tid >> 4)) * ldb + n0 + (tid & 15) * 4);
        } else {
            pb = *reinterpret_cast<const float4*>(
                Bm + (size_t)(n0 + (tid >> 2)) * ldb + k0 + (tid & 3) * 4);
        }
    }

    const int ntiles = kchunk / 16;
    for (int t = 0; t < ntiles; ++t) {
        // store prefetched tile to smem
#pragma unroll
        for (int c = 0; c < 2; ++c) {
            As[ak + c * 4 + 0][am] = (&pa[c].x)[0];
            As[ak + c * 4 + 1][am] = (&pa[c].x)[1];
            As[ak + c * 4 + 2][am] = (&pa[c].x)[2];
            As[ak + c * 4 + 3][am] = (&pa[c].x)[3];
        }
        if (!TB) {
            const int kk = tid >> 4, ng4 = (tid & 15) * 4;
            Bs[kk][ng4 + 0] = pb.x;
            Bs[kk][ng4 + 1] = pb.y;
            Bs[kk][ng4 + 2] = pb.z;
            Bs[kk][ng4 + 3] = pb.w;
        } else {
            const int nn = tid >> 2, cg4 = (tid & 3) * 4;
            Bs[cg4 + 0][nn] = pb.x;
            Bs[cg4 + 1][nn] = pb.y;
            Bs[cg4 + 2][nn] = pb.z;
            Bs[cg4 + 3][nn] = pb.w;
        }
        __syncthreads();

        // prefetch next tile
        if (t + 1 < ntiles) {
            const int kk0 = k0 + (t + 1) * 16;
            const float* ap = A + (size_t)am * lda + kk0 + ak;
            pa[0] = *reinterpret_cast<const float4*>(ap);
            pa[1] = *reinterpret_cast<const float4*>(ap + 4);
            if (!TB) {
                pb = *reinterpret_cast<const float4*>(
                    Bm + (size_t)(kk0 + (tid >> 4)) * ldb + n0 + (tid & 15) * 4);
            } else {
                pb = *reinterpret_cast<const float4*>(
                    Bm + (size_t)(n0 + (tid >> 2)) * ldb + kk0 + (tid & 3) * 4);
            }
        }

        // compute
#pragma unroll
        for (int kk = 0; kk < 16; ++kk) {
            float av[8];
            *reinterpret_cast<float4*>(&av[0]) =
                *reinterpret_cast<const float4*>(&As[kk][my8]);
            *reinterpret_cast<float4*>(&av[4]) =
                *reinterpret_cast<const float4*>(&As[kk][my8 + 4]);
            float4 bq = *reinterpret_cast<const float4*>(&Bs[kk][nx4]);
            const float bv[4] = {bq.x, bq.y, bq.z, bq.w};
#pragma unroll
            for (int i = 0; i < 8; ++i)
#pragma unroll
                for (int j = 0; j < 4; ++j)
                    acc[i][j] += av[i] * bv[j];
        }
        __syncthreads();
    }

    // write partial C
#pragma unroll
    for (int i = 0; i < 8; ++i) {
        const int m = my8 + i;
        float4 v = make_float4(acc[i][0], acc[i][1], acc[i][2], acc[i][3]);
        *reinterpret_cast<float4*>(C + (size_t)m * N + n0 + nx4) = v;
    }
}

// ---------------------------------------------------------------------------
// LIF update for both hidden layers. blockIdx.y = layer (0 or 1).
// Sums split-K partials of ti and applies the elementwise LIF dynamics.
// ---------------------------------------------------------------------------
__global__ void lif_kernel()
{
    const size_t idx = (size_t)blockIdx.x * blockDim.x + threadIdx.x;
    const int layer = blockIdx.y;

    float ti;
    size_t vo;
    if (layer == 0) {
        const float* t = g_pool + OFF_TI1;
        ti = t[idx] + t[S1 + idx] + t[2 * S1 + idx] + t[3 * S1 + idx]
           - g_pool[OFF_EG1 + idx] - g_pool[OFF_ED1 + idx];
        vo = OFF_V1;
    } else {
        const float* t = g_pool + OFF_TI2;
        ti = t[idx] + t[S1 + idx] + t[2 * S1 + idx] + t[3 * S1 + idx]
           - g_pool[OFF_EG2 + idx] - g_pool[OFF_ED2 + idx];
        vo = OFF_V2;
    }

    float j = g_pool[vo + 2 * S1 + idx];
    j = j + 0.1f * (ti - j);                 // dt/tau_j=0.1, kappa_j=1
    float v = g_pool[vo + idx];
    float r = g_pool[vo + 3 * S1 + idx];
    const bool refr = r > 0.0f;
    const float vn = v + 0.05f * (j - v);    // dt/tau_m=0.05, gamma=R=1
    v = refr ? v : vn;
    const float s = (!refr && v > 1.0f) ? 1.0f : 0.0f;
    v = v * (1.0f - s);
    r = fmaxf(r - 1.0f, 0.0f);
    if (s != 0.0f) r = 2.0f;                 // T_r
    float tr = g_pool[vo + S1 + idx];
    tr = tr - tr * (1.0f / 20.0f) + s;       // tau_tr=20

    g_pool[vo + idx]          = v;
    g_pool[vo + S1 + idx]     = tr;
    g_pool[vo + 2 * S1 + idx] = j;
    g_pool[vo + 3 * S1 + idx] = r;
    g_pool[vo + 4 * S1 + idx] = s;
}

// ---------------------------------------------------------------------------
// Phase-2 error recomputation (elementwise), sums phase-2 GEMM partials.
// Grid over B*D1; smaller dims handled by predicates. On the final step,
// also writes ed3 to d_out.
// ---------------------------------------------------------------------------
__global__ void err_kernel(const float* __restrict__ x,
                           const float* __restrict__ y,
                           float* __restrict__ out)
{
    const size_t idx = (size_t)blockIdx.x * blockDim.x + threadIdx.x;
    const int n = (int)(idx & 4095);
    const int b = (int)(idx >> 12);

    const float tr1 = g_pool[OFF_TR1 + idx];
    const float tr2 = g_pool[OFF_TR2 + idx];

    const float g2 = g_pool[OFF_G2 + idx] + g_pool[OFF_G2 + S1 + idx];
    g_pool[OFF_EG1 + idx] = 0.5f * (tr1 - g2);

    const float g3 = g_pool[OFF_G3 + idx] + g_pool[OFF_G3 + S1 + idx];
    g_pool[OFF_ED2 + idx] = 0.5f * (tr2 - g3);

    g_pool[OFF_ED1 + idx] = 0.5f * (tr1 - g_pool[OFF_C0 + idx]);
    g_pool[OFF_EG2 + idx] = 0.5f * (tr2 - g_pool[OFF_C1 + idx]);

    if (n < DD0) {
        const size_t i0 = (size_t)b * DD0 + n;
        float zd = g_pool[OFF_ZD + i0];
        zd = zd - zd * 0.1f + x[i0];          // tau_data=10
        g_pool[OFF_ZD + i0] = zd;
        const float g1 = g_pool[OFF_G1 + i0] + g_pool[OFF_G1 + S0 + i0] +
                         g_pool[OFF_G1 + 2 * S0 + i0] + g_pool[OFF_G1 + 3 * S0 + i0];
        g_pool[OFF_EG0 + i0] = 0.5f * (zd - g1);
    }
    if (n < DD3) {
        const size_t i3 = (size_t)b * DD3 + n;
        float zl = g_pool[OFF_ZL + i3];
        zl = zl - zl * 0.1f + y[i3];
        g_pool[OFF_ZL + i3] = zl;
        float g4 = 0.0f;
#pragma unroll
        for (int p = 0; p < 16; ++p) g4 += g_pool[OFF_G4 + (size_t)p * S3 + i3];
        const float e = 0.5f * (zl - g4);
        g_pool[OFF_ED3 + i3] = e;
        if (out) out[i3] = e;
    }
}

// ---------------------------------------------------------------------------
// Host launcher (graph-capturable: kernels + async memset only).
// ---------------------------------------------------------------------------
extern "C" void kernel_launch(void* const* d_in, const int* in_sizes, int n_in,
                              void* d_out, int out_size)
{
    const float* x  = (const float*)d_in[0];
    const float* y  = (const float*)d_in[1];
    const float* W0 = (const float*)d_in[2];
    const float* W1 = (const float*)d_in[3];
    const float* W2 = (const float*)d_in[4];
    const float* V0 = (const float*)d_in[5];
    const float* V1 = (const float*)d_in[6];
    const float* V2 = (const float*)d_in[7];
    float* out = (float*)d_out;
    (void)in_sizes; (void)n_in; (void)out_size;

    float* pool = nullptr;
    cudaGetSymbolAddress((void**)&pool, g_pool);

    // zero all persistent state (v/tr/j/r/s, errors, z traces)
    cudaMemsetAsync(pool, 0, ZERO_FLOATS * sizeof(float), 0);

    auto launch_nn = [&](const float* A, int lda, const float* Bm, int ldb,
                         float* C, int N, int K, int ks) {
        dim3 grid((unsigned)(N / 64), (unsigned)ks);
        gemm128<false><<<grid, 256>>>(A, lda, Bm, ldb, C, N, K / ks);
    };
    auto launch_nt = [&](const float* A, int lda, const float* Bm, int ldb,
                         float* C, int N, int K, int ks) {
        dim3 grid((unsigned)(N / 64), (unsigned)ks);
        gemm128<true><<<grid, 256>>>(A, lda, Bm, ldb, C, N, K / ks);
    };

    // step-invariant GEMMs (hoisted out of the 16-step loop):
    // C0 = x @ V0^T : [128,2048] x [2048,4096];  V0 rows length 2048
    launch_nt(x, DD0, V0, DD0, pool + OFF_C0, DD1, DD0, 1);
    // C1 = y @ W2^T : [128,512] x [512,4096];    W2 rows length 512
    launch_nt(y, DD3, W2, DD3, pool + OFF_C1, DD1, DD3, 1);

    const unsigned EW_BLOCKS = (unsigned)(S1 / 256);

    for (int step = 0; step < 16; ++step) {
        // phase 1: synaptic currents (split-K partials into ti1/ti2)
        launch_nn(pool + OFF_EG0, DD0, W0, DD1, pool + OFF_TI1,            DD1, DD0, 2);
        launch_nn(pool + OFF_ED2, DD1, V1, DD1, pool + OFF_TI1 + 2 * S1,   DD1, DD1, 2);
        launch_nn(pool + OFF_EG1, DD1, W1, DD1, pool + OFF_TI2,            DD1, DD1, 2);
        launch_nn(pool + OFF_ED3, DD3, V2, DD1, pool + OFF_TI2 + 2 * S1,   DD1, DD3, 2);

        lif_kernel<<<dim3(EW_BLOCKS, 2), 256>>>();

        // phase 2: error-path GEMMs (transposed weights, spike inputs)
        launch_nt(pool + OFF_SP1, DD1, W0, DD1, pool + OFF_G1, DD0, DD1, 4);
        launch_nt(pool + OFF_SP2, DD1, W1, DD1, pool + OFF_G2, DD1, DD1, 2);
        launch_nt(pool + OFF_SP1, DD1, V1, DD1, pool + OFF_G3, DD1, DD1, 2);
        launch_nt(pool + OFF_SP2, DD1, V2, DD1, pool + OFF_G4, DD3, DD1, 16);

        err_kernel<<<EW_BLOCKS, 256>>>(x, y, step == 15 ? out : nullptr);
    }
}

// round 7
// speedup vs baseline: 1.3123x; 1.3123x over previous
#include <cuda_runtime.h>
#include <cstddef>

// ---------------------------------------------------------------------------
// bPC_SNN: 16-step predictive-coding SNN recurrence.
// B=128, d0=2048, d1=d2=4096, d3=512. Output = final ed3 [128,512] f32.
// ---------------------------------------------------------------------------

#define BATCH 128
#define DD0   2048
#define DD1   4096
#define DD3   512

static constexpr size_t S1 = (size_t)BATCH * DD1;   // 524288
static constexpr size_t S0 = (size_t)BATCH * DD0;   // 262144
static constexpr size_t S3 = (size_t)BATCH * DD3;   // 65536

// pool layout (floats). Zero-initialized prefix first.
static constexpr size_t OFF_V1  = 0;
static constexpr size_t OFF_TR1 = 1 * S1;
static constexpr size_t OFF_J1  = 2 * S1;
static constexpr size_t OFF_R1  = 3 * S1;
static constexpr size_t OFF_SP1 = 4 * S1;
static constexpr size_t OFF_V2  = 5 * S1;
static constexpr size_t OFF_TR2 = 6 * S1;
static constexpr size_t OFF_J2  = 7 * S1;
static constexpr size_t OFF_R2  = 8 * S1;
static constexpr size_t OFF_SP2 = 9 * S1;
static constexpr size_t OFF_EG1 = 10 * S1;
static constexpr size_t OFF_ED1 = 11 * S1;
static constexpr size_t OFF_ED2 = 12 * S1;
static constexpr size_t OFF_EG2 = 13 * S1;
static constexpr size_t OFF_EG0 = 14 * S1;
static constexpr size_t OFF_ZD  = 14 * S1 + S0;
static constexpr size_t OFF_ED3 = 14 * S1 + 2 * S0;
static constexpr size_t OFF_ZL  = 14 * S1 + 2 * S0 + S3;
static constexpr size_t ZERO_FLOATS = 14 * S1 + 2 * S0 + 2 * S3;

// scratch (fully overwritten before use each step; no zeroing needed)
static constexpr int PTI1A = 8;   // eg0@W0 split-K parts
static constexpr int PTI1B = 8;   // ed2@V1 parts
static constexpr int PTI1  = PTI1A + PTI1B;        // 16
static constexpr int PTI2A = 8;   // eg1@W1 parts
static constexpr int PTI2B = 4;   // ed3@V2 parts
static constexpr int PTI2  = PTI2A + PTI2B;        // 12
static constexpr int PG1 = 8, PG2 = 8, PG3 = 8, PG4 = 32;

static constexpr size_t OFF_TI1 = ZERO_FLOATS;            // PTI1 parts of [B,D1]
static constexpr size_t OFF_TI2 = OFF_TI1 + PTI1 * S1;    // PTI2 parts
static constexpr size_t OFF_G2  = OFF_TI2 + PTI2 * S1;    // PG2 parts (s2@W1^T)
static constexpr size_t OFF_G3  = OFF_G2 + PG2 * S1;      // PG3 parts (s1@V1^T)
static constexpr size_t OFF_C0  = OFF_G3 + PG3 * S1;      // x@V0^T (const)
static constexpr size_t OFF_C1  = OFF_C0 + S1;            // y@W2^T (const)
static constexpr size_t OFF_G1  = OFF_C1 + S1;            // PG1 parts of [B,D0]
static constexpr size_t OFF_G4  = OFF_G1 + PG1 * S0;      // PG4 parts of [B,D3]
static constexpr size_t POOL_FLOATS = OFF_G4 + PG4 * S3;  // ~138 MB

__device__ float g_pool[POOL_FLOATS];

// ---------------------------------------------------------------------------
// Generic M=128 GEMM, partial-K output (deterministic split-K).
//   C_part[by][b][n] = sum_{k in chunk(by)} A[b][k] * Bop[k][n]
//   NN: Bop[k][n] = Bm[k*ldb + n]      NT: Bop[k][n] = Bm[n*ldb + k]
// Tile: BM=128, BN=64, BK=16. 256 threads, 8x4 microtile, reg prefetch.
// Requires: N % 64 == 0, kchunk % 16 == 0.
// ---------------------------------------------------------------------------
template <bool TB>
__global__ __launch_bounds__(256)
void gemm128(const float* __restrict__ A, int lda,
             const float* __restrict__ Bm, int ldb,
             float* __restrict__ C, int N, int kchunk)
{
    __shared__ float As[16][128];
    __shared__ float Bs[16][68];   // 64 + pad

    const int tid = threadIdx.x;
    const int n0  = blockIdx.x * 64;
    const int k0  = blockIdx.y * kchunk;
    C += (size_t)blockIdx.y * 128 * N;

    const int my8 = (tid >> 4) * 8;   // m offset (0..120)
    const int nx4 = (tid & 15) * 4;   // n offset (0..60)
    const int am = tid & 127;
    const int ak = (tid >> 7) * 8;

    float acc[8][4];
#pragma unroll
    for (int i = 0; i < 8; ++i)
#pragma unroll
        for (int j = 0; j < 4; ++j) acc[i][j] = 0.0f;

    float4 pa[2];
    float4 pb;

    {
        const float* ap = A + (size_t)am * lda + k0 + ak;
        pa[0] = *reinterpret_cast<const float4*>(ap);
        pa[1] = *reinterpret_cast<const float4*>(ap + 4);
        if (!TB) {
            pb = *reinterpret_cast<const float4*>(
                Bm + (size_t)(k0 + (tid >> 4)) * ldb + n0 + (tid & 15) * 4);
        } else {
            pb = *reinterpret_cast<const float4*>(
                Bm + (size_t)(n0 + (tid >> 2)) * ldb + k0 + (tid & 3) * 4);
        }
    }

    const int ntiles = kchunk / 16;
    for (int t = 0; t < ntiles; ++t) {
#pragma unroll
        for (int c = 0; c < 2; ++c) {
            As[ak + c * 4 + 0][am] = (&pa[c].x)[0];
            As[ak + c * 4 + 1][am] = (&pa[c].x)[1];
            As[ak + c * 4 + 2][am] = (&pa[c].x)[2];
            As[ak + c * 4 + 3][am] = (&pa[c].x)[3];
        }
        if (!TB) {
            const int kk = tid >> 4, ng4 = (tid & 15) * 4;
            Bs[kk][ng4 + 0] = pb.x;
            Bs[kk][ng4 + 1] = pb.y;
            Bs[kk][ng4 + 2] = pb.z;
            Bs[kk][ng4 + 3] = pb.w;
        } else {
            const int nn = tid >> 2, cg4 = (tid & 3) * 4;
            Bs[cg4 + 0][nn] = pb.x;
            Bs[cg4 + 1][nn] = pb.y;
            Bs[cg4 + 2][nn] = pb.z;
            Bs[cg4 + 3][nn] = pb.w;
        }
        __syncthreads();

        if (t + 1 < ntiles) {
            const int kk0 = k0 + (t + 1) * 16;
            const float* ap = A + (size_t)am * lda + kk0 + ak;
            pa[0] = *reinterpret_cast<const float4*>(ap);
            pa[1] = *reinterpret_cast<const float4*>(ap + 4);
            if (!TB) {
                pb = *reinterpret_cast<const float4*>(
                    Bm + (size_t)(kk0 + (tid >> 4)) * ldb + n0 + (tid & 15) * 4);
            } else {
                pb = *reinterpret_cast<const float4*>(
                    Bm + (size_t)(n0 + (tid >> 2)) * ldb + kk0 + (tid & 3) * 4);
            }
        }

#pragma unroll
        for (int kk = 0; kk < 16; ++kk) {
            float av[8];
            *reinterpret_cast<float4*>(&av[0]) =
                *reinterpret_cast<const float4*>(&As[kk][my8]);
            *reinterpret_cast<float4*>(&av[4]) =
                *reinterpret_cast<const float4*>(&As[kk][my8 + 4]);
            float4 bq = *reinterpret_cast<const float4*>(&Bs[kk][nx4]);
            const float bv[4] = {bq.x, bq.y, bq.z, bq.w};
#pragma unroll
            for (int i = 0; i < 8; ++i)
#pragma unroll
                for (int j = 0; j < 4; ++j)
                    acc[i][j] += av[i] * bv[j];
        }
        __syncthreads();
    }

#pragma unroll
    for (int i = 0; i < 8; ++i) {
        const int m = my8 + i;
        float4 v = make_float4(acc[i][0], acc[i][1], acc[i][2], acc[i][3]);
        *reinterpret_cast<float4*>(C + (size_t)m * N + n0 + nx4) = v;
    }
}

// ---------------------------------------------------------------------------
// Collapse pre-loop constant GEMM partials: C0 = sum(TI1[0..7]),
// C1 = sum(TI2[0..3]). Runs once before the step loop.
// ---------------------------------------------------------------------------
__global__ void reduce_const_kernel()
{
    const size_t idx = (size_t)blockIdx.x * blockDim.x + threadIdx.x;
    float c0 = 0.0f;
#pragma unroll
    for (int p = 0; p < 8; ++p) c0 += g_pool[OFF_TI1 + (size_t)p * S1 + idx];
    g_pool[OFF_C0 + idx] = c0;
    float c1 = 0.0f;
#pragma unroll
    for (int p = 0; p < 4; ++p) c1 += g_pool[OFF_TI2 + (size_t)p * S1 + idx];
    g_pool[OFF_C1 + idx] = c1;
}

// ---------------------------------------------------------------------------
// LIF update for both hidden layers. blockIdx.y = layer (0 or 1).
// ---------------------------------------------------------------------------
__global__ void lif_kernel()
{
    const size_t idx = (size_t)blockIdx.x * blockDim.x + threadIdx.x;
    const int layer = blockIdx.y;

    float ti;
    size_t vo;
    if (layer == 0) {
        const float* t = g_pool + OFF_TI1;
        float s = 0.0f;
#pragma unroll
        for (int p = 0; p < PTI1; ++p) s += t[(size_t)p * S1 + idx];
        ti = s - g_pool[OFF_EG1 + idx] - g_pool[OFF_ED1 + idx];
        vo = OFF_V1;
    } else {
        const float* t = g_pool + OFF_TI2;
        float s = 0.0f;
#pragma unroll
        for (int p = 0; p < PTI2; ++p) s += t[(size_t)p * S1 + idx];
        ti = s - g_pool[OFF_EG2 + idx] - g_pool[OFF_ED2 + idx];
        vo = OFF_V2;
    }

    float j = g_pool[vo + 2 * S1 + idx];
    j = j + 0.1f * (ti - j);                 // dt/tau_j=0.1, kappa_j=1
    float v = g_pool[vo + idx];
    float r = g_pool[vo + 3 * S1 + idx];
    const bool refr = r > 0.0f;
    const float vn = v + 0.05f * (j - v);    // dt/tau_m=0.05, gamma=R=1
    v = refr ? v : vn;
    const float s = (!refr && v > 1.0f) ? 1.0f : 0.0f;
    v = v * (1.0f - s);
    r = fmaxf(r - 1.0f, 0.0f);
    if (s != 0.0f) r = 2.0f;                 // T_r
    float tr = g_pool[vo + S1 + idx];
    tr = tr - tr * (1.0f / 20.0f) + s;       // tau_tr=20

    g_pool[vo + idx]          = v;
    g_pool[vo + S1 + idx]     = tr;
    g_pool[vo + 2 * S1 + idx] = j;
    g_pool[vo + 3 * S1 + idx] = r;
    g_pool[vo + 4 * S1 + idx] = s;
}

// ---------------------------------------------------------------------------
// Phase-2 error recomputation. On the final step, also writes ed3 to d_out.
// ---------------------------------------------------------------------------
__global__ void err_kernel(const float* __restrict__ x,
                           const float* __restrict__ y,
                           float* __restrict__ out)
{
    const size_t idx = (size_t)blockIdx.x * blockDim.x + threadIdx.x;
    const int n = (int)(idx & 4095);
    const int b = (int)(idx >> 12);

    const float tr1 = g_pool[OFF_TR1 + idx];
    const float tr2 = g_pool[OFF_TR2 + idx];

    float g2 = 0.0f;
#pragma unroll
    for (int p = 0; p < PG2; ++p) g2 += g_pool[OFF_G2 + (size_t)p * S1 + idx];
    g_pool[OFF_EG1 + idx] = 0.5f * (tr1 - g2);

    float g3 = 0.0f;
#pragma unroll
    for (int p = 0; p < PG3; ++p) g3 += g_pool[OFF_G3 + (size_t)p * S1 + idx];
    g_pool[OFF_ED2 + idx] = 0.5f * (tr2 - g3);

    g_pool[OFF_ED1 + idx] = 0.5f * (tr1 - g_pool[OFF_C0 + idx]);
    g_pool[OFF_EG2 + idx] = 0.5f * (tr2 - g_pool[OFF_C1 + idx]);

    if (n < DD0) {
        const size_t i0 = (size_t)b * DD0 + n;
        float zd = g_pool[OFF_ZD + i0];
        zd = zd - zd * 0.1f + x[i0];          // tau_data=10
        g_pool[OFF_ZD + i0] = zd;
        float g1 = 0.0f;
#pragma unroll
        for (int p = 0; p < PG1; ++p) g1 += g_pool[OFF_G1 + (size_t)p * S0 + i0];
        g_pool[OFF_EG0 + i0] = 0.5f * (zd - g1);
    }
    if (n < DD3) {
        const size_t i3 = (size_t)b * DD3 + n;
        float zl = g_pool[OFF_ZL + i3];
        zl = zl - zl * 0.1f + y[i3];
        g_pool[OFF_ZL + i3] = zl;
        float g4 = 0.0f;
#pragma unroll
        for (int p = 0; p < PG4; ++p) g4 += g_pool[OFF_G4 + (size_t)p * S3 + i3];
        const float e = 0.5f * (zl - g4);
        g_pool[OFF_ED3 + i3] = e;
        if (out) out[i3] = e;
    }
}

// ---------------------------------------------------------------------------
// Host launcher (graph-capturable: kernels + async memset only).
// ---------------------------------------------------------------------------
extern "C" void kernel_launch(void* const* d_in, const int* in_sizes, int n_in,
                              void* d_out, int out_size)
{
    const float* x  = (const float*)d_in[0];
    const float* y  = (const float*)d_in[1];
    const float* W0 = (const float*)d_in[2];
    const float* W1 = (const float*)d_in[3];
    const float* W2 = (const float*)d_in[4];
    const float* V0 = (const float*)d_in[5];
    const float* V1 = (const float*)d_in[6];
    const float* V2 = (const float*)d_in[7];
    float* out = (float*)d_out;
    (void)in_sizes; (void)n_in; (void)out_size;

    float* pool = nullptr;
    cudaGetSymbolAddress((void**)&pool, g_pool);

    // zero all persistent state (v/tr/j/r/s, errors, z traces)
    cudaMemsetAsync(pool, 0, ZERO_FLOATS * sizeof(float), 0);

    auto launch_nn = [&](const float* A, int lda, const float* Bm, int ldb,
                         float* C, int N, int K, int ks) {
        dim3 grid((unsigned)(N / 64), (unsigned)ks);
        gemm128<false><<<grid, 256>>>(A, lda, Bm, ldb, C, N, K / ks);
    };
    auto launch_nt = [&](const float* A, int lda, const float* Bm, int ldb,
                         float* C, int N, int K, int ks) {
        dim3 grid((unsigned)(N / 64), (unsigned)ks);
        gemm128<true><<<grid, 256>>>(A, lda, Bm, ldb, C, N, K / ks);
    };

    const unsigned EW_BLOCKS = (unsigned)(S1 / 256);

    // step-invariant GEMMs (hoisted): partials into TI scratch, then collapse.
    // C0 = x @ V0^T : [128,2048]x[2048,4096]
    launch_nt(x, DD0, V0, DD0, pool + OFF_TI1, DD1, DD0, 8);
    // C1 = y @ W2^T : [128,512]x[512,4096]
    launch_nt(y, DD3, W2, DD3, pool + OFF_TI2, DD1, DD3, 4);
    reduce_const_kernel<<<EW_BLOCKS, 256>>>();

    for (int step = 0; step < 16; ++step) {
        // phase 1: synaptic currents (split-K partials into ti1/ti2)
        launch_nn(pool + OFF_EG0, DD0, W0, DD1, pool + OFF_TI1,               DD1, DD0, PTI1A);
        launch_nn(pool + OFF_ED2, DD1, V1, DD1, pool + OFF_TI1 + PTI1A * S1,  DD1, DD1, PTI1B);
        launch_nn(pool + OFF_EG1, DD1, W1, DD1, pool + OFF_TI2,               DD1, DD1, PTI2A);
        launch_nn(pool + OFF_ED3, DD3, V2, DD1, pool + OFF_TI2 + PTI2A * S1,  DD1, DD3, PTI2B);

        lif_kernel<<<dim3(EW_BLOCKS, 2), 256>>>();

        // phase 2: error-path GEMMs (transposed weights, spike inputs)
        launch_nt(pool + OFF_SP1, DD1, W0, DD1, pool + OFF_G1, DD0, DD1, PG1);
        launch_nt(pool + OFF_SP2, DD1, W1, DD1, pool + OFF_G2, DD1, DD1, PG2);
        launch_nt(pool + OFF_SP1, DD1, V1, DD1, pool + OFF_G3, DD1, DD1, PG3);
        launch_nt(pool + OFF_SP2, DD1, V2, DD1, pool + OFF_G4, DD3, DD1, PG4);

        err_kernel<<<EW_BLOCKS, 256>>>(x, y, step == 15 ? out : nullptr);
    }
}

// round 9
// speedup vs baseline: 1.4377x; 1.0956x over previous
#include <cuda_runtime.h>
#include <cuda_bf16.h>
#include <cstdint>
#include <cstddef>

// ---------------------------------------------------------------------------
// bPC_SNN: 16-step predictive-coding SNN recurrence.
// B=128, d0=2048, d1=d2=4096, d3=512. Output = final ed3 [128,512] f32.
// GEMMs on tensor cores via exact split-bf16 (Ozaki scheme):
//   phase-2: spikes are {0,1} (exact in bf16) x 3 weight planes -> fp32-exact.
//   phase-1: 3-way split of A, 6 cross terms -> ~2^-24 relative error.
// ---------------------------------------------------------------------------

#define BATCH 128
#define DD0   2048
#define DD1   4096
#define DD3   512

static constexpr size_t S1 = (size_t)BATCH * DD1;   // 524288
static constexpr size_t S0 = (size_t)BATCH * DD0;   // 262144
static constexpr size_t S3 = (size_t)BATCH * DD3;   // 65536

static constexpr size_t szW0 = (size_t)DD0 * DD1;   // 8M
static constexpr size_t szW1 = (size_t)DD1 * DD1;   // 16M
static constexpr size_t szV1 = (size_t)DD1 * DD1;   // 16M
static constexpr size_t szV2 = (size_t)DD3 * DD1;   // 2M

// ---------------- fp32 pool ----------------
static constexpr size_t OFF_V1  = 0;
static constexpr size_t OFF_TR1 = 1 * S1;
static constexpr size_t OFF_J1  = 2 * S1;
static constexpr size_t OFF_R1  = 3 * S1;
static constexpr size_t OFF_SP1 = 4 * S1;   // unused now, kept in zero range
static constexpr size_t OFF_V2  = 5 * S1;
static constexpr size_t OFF_TR2 = 6 * S1;
static constexpr size_t OFF_J2  = 7 * S1;
static constexpr size_t OFF_R2  = 8 * S1;
static constexpr size_t OFF_SP2 = 9 * S1;   // unused
static constexpr size_t OFF_EG1 = 10 * S1;
static constexpr size_t OFF_ED1 = 11 * S1;
static constexpr size_t OFF_ED2 = 12 * S1;
static constexpr size_t OFF_EG2 = 13 * S1;
static constexpr size_t OFF_EG0 = 14 * S1;  // unused fp32 slot
static constexpr size_t OFF_ZD  = 14 * S1 + S0;
static constexpr size_t OFF_ED3 = 14 * S1 + 2 * S0;
static constexpr size_t OFF_ZL  = 14 * S1 + 2 * S0 + S3;
static constexpr size_t ZERO_FLOATS = 14 * S1 + 2 * S0 + 2 * S3;

// split-K part counts
static constexpr int PTI1A = 4, PTI1B = 4, PTI1 = 8;
static constexpr int PTI2A = 4, PTI2B = 4, PTI2 = 8;
static constexpr int PG1 = 8, PG2 = 4, PG3 = 4, PG4 = 32;

static constexpr size_t OFF_TI1 = ZERO_FLOATS;          // 8 parts [B,D1]
static constexpr size_t OFF_TI2 = OFF_TI1 + 8 * S1;     // 8 parts
static constexpr size_t OFF_G2  = OFF_TI2 + 8 * S1;     // 4 parts
static constexpr size_t OFF_G3  = OFF_G2 + 4 * S1;      // 4 parts
static constexpr size_t OFF_C0  = OFF_G3 + 4 * S1;      // const x@V0^T
static constexpr size_t OFF_C1  = OFF_C0 + S1;          // const y@W2^T
static constexpr size_t OFF_G1  = OFF_C1 + S1;          // 8 parts [B,D0]
static constexpr size_t OFF_G4  = OFF_G1 + 8 * S0;      // 32 parts [B,D3]
static constexpr size_t POOL_FLOATS = OFF_G4 + 32 * S3;

__device__ float g_pool[POOL_FLOATS];

// ---------------- bf16 pool ----------------
// activation splits first (zeroed once), then weight planes (written pre-loop)
static constexpr size_t OFFB_EG0S = 0;                      // 3 x S0
static constexpr size_t OFFB_ED2S = OFFB_EG0S + 3 * S0;     // 3 x S1
static constexpr size_t OFFB_EG1S = OFFB_ED2S + 3 * S1;     // 3 x S1
static constexpr size_t OFFB_ED3S = OFFB_EG1S + 3 * S1;     // 3 x S3
static constexpr size_t OFFB_SP1  = OFFB_ED3S + 3 * S3;     // 1 x S1
static constexpr size_t OFFB_SP2  = OFFB_SP1 + S1;          // 1 x S1
static constexpr size_t BZERO_ELEMS = OFFB_SP2 + S1;
static constexpr size_t OFFB_W0NT = BZERO_ELEMS;            // 3 planes [R,C]
static constexpr size_t OFFB_W0NN = OFFB_W0NT + 3 * szW0;   // 3 planes [C,R]
static constexpr size_t OFFB_W1NT = OFFB_W0NN + 3 * szW0;
static constexpr size_t OFFB_W1NN = OFFB_W1NT + 3 * szW1;
static constexpr size_t OFFB_V1NT = OFFB_W1NN + 3 * szW1;
static constexpr size_t OFFB_V1NN = OFFB_V1NT + 3 * szV1;
static constexpr size_t OFFB_V2NT = OFFB_V1NN + 3 * szV1;
static constexpr size_t OFFB_V2NN = OFFB_V2NT + 3 * szV2;
static constexpr size_t BPOOL_ELEMS = OFFB_V2NN + 3 * szV2;

__device__ __align__(16) __nv_bfloat16 g_bpool[BPOOL_ELEMS];

// ---------------------------------------------------------------------------
// helpers
// ---------------------------------------------------------------------------
__device__ __forceinline__ uint32_t su32(const void* p) {
    return (uint32_t)__cvta_generic_to_shared(p);
}

__device__ __forceinline__ void split3(float a, __nv_bfloat16& h0,
                                       __nv_bfloat16& h1, __nv_bfloat16& h2) {
    h0 = __float2bfloat16_rn(a);
    float r1 = a - __bfloat162float(h0);
    h1 = __float2bfloat16_rn(r1);
    float r2 = r1 - __bfloat162float(h1);
    h2 = __float2bfloat16_rn(r2);
}

#define LDSM_X4(r0, r1, r2, r3, addr)                                        \
    asm volatile("ldmatrix.sync.aligned.m8n8.x4.shared.b16 {%0,%1,%2,%3}, [%4];\n" \
                 : "=r"(r0), "=r"(r1), "=r"(r2), "=r"(r3) : "r"(addr))

#define MMA16816(d, a, b)                                                    \
    asm volatile("mma.sync.aligned.m16n8k16.row.col.f32.bf16.bf16.f32 "      \
                 "{%0,%1,%2,%3},{%4,%5,%6,%7},{%8,%9},{%0,%1,%2,%3};\n"      \
                 : "+f"(d[0]), "+f"(d[1]), "+f"(d[2]), "+f"(d[3])            \
                 : "r"(a[0]), "r"(a[1]), "r"(a[2]), "r"(a[3]),               \
                   "r"(b[0]), "r"(b[1]))

// ---------------------------------------------------------------------------
// Tensor-core GEMM: C_part = sum_terms A_lev @ B_lev^T over k-chunk.
//   A: [128, K] bf16 planes (stride aStride), row pitch K
//   B: [N, K]  bf16 planes (stride bStride), row pitch K  (i.e. B^T col-major)
// PHASE 1: 6 terms (a0b0, a0b1, a1b0, a0b2, a1b1, a2b0)
// PHASE 2: 3 terms (a0b0, a0b1, a0b2)  -- A has a single (spike) plane
// Tile 128x64x32, 256 threads (8 warps: 4m x 2n), double-buffered smem.
// ---------------------------------------------------------------------------
template <int PHASE>
__global__ __launch_bounds__(256)
void gemm_mma(const __nv_bfloat16* __restrict__ Ab, size_t aStride, int K,
              const __nv_bfloat16* __restrict__ Bb, size_t bStride,
              float* __restrict__ C, int N, int kchunk)
{
    constexpr int NTERMS = (PHASE == 1) ? 6 : 3;
    __shared__ __nv_bfloat16 sA[2][128][40];
    __shared__ __nv_bfloat16 sB[2][64][40];

    const int tid  = threadIdx.x;
    const int lane = tid & 31;
    const int warp = tid >> 5;
    const int wm   = warp >> 1;          // 0..3
    const int wn   = warp & 1;           // 0..1
    const int n0   = blockIdx.x * 64;
    const int k0   = blockIdx.y * kchunk;
    C += (size_t)blockIdx.y * 128 * N;

    // loader mapping: A two 16B chunks per thread, B one 16B chunk
    const int arow = tid >> 1;           // 0..127
    const int ac   = (tid & 1) * 2;      // chunk 0 or 2 (plus next)
    const int brow = tid >> 2;           // 0..63
    const int bc   = tid & 3;

    float acc[2][4][4];
#pragma unroll
    for (int i = 0; i < 2; ++i)
#pragma unroll
        for (int j = 0; j < 4; ++j)
#pragma unroll
            for (int q = 0; q < 4; ++q) acc[i][j][q] = 0.0f;

    const int KT  = kchunk / 32;
    const int TOT = NTERMS * KT;

    uint4 ra0, ra1, rb;

    auto glo = [&](int it) {
        int t  = it / KT;
        int kt = it - t * KT;
        int al, bl;
        if (PHASE == 2) { al = 0; bl = t; }
        else {
            const int A6[6] = {0, 0, 1, 0, 1, 2};
            const int B6[6] = {0, 1, 0, 2, 1, 0};
            al = A6[t]; bl = B6[t];
        }
        const __nv_bfloat16* At = Ab + (size_t)al * aStride;
        const __nv_bfloat16* Bt = Bb + (size_t)bl * bStride;
        const int kb = k0 + kt * 32;
        const __nv_bfloat16* ap = At + (size_t)arow * K + kb + ac * 8;
        ra0 = *reinterpret_cast<const uint4*>(ap);
        ra1 = *reinterpret_cast<const uint4*>(ap + 8);
        rb  = *reinterpret_cast<const uint4*>(Bt + (size_t)(n0 + brow) * K + kb + bc * 8);
    };
    auto sst = [&](int buf) {
        *reinterpret_cast<uint4*>(&sA[buf][arow][ac * 8])     = ra0;
        *reinterpret_cast<uint4*>(&sA[buf][arow][ac * 8 + 8]) = ra1;
        *reinterpret_cast<uint4*>(&sB[buf][brow][bc * 8])     = rb;
    };

    glo(0);
    sst(0);
    __syncthreads();

    for (int it = 0; it < TOT; ++it) {
        const int buf = it & 1;
        if (it + 1 < TOT) glo(it + 1);

#pragma unroll
        for (int ks = 0; ks < 32; ks += 16) {
            uint32_t a0[4], a1[4], b[8];
            {
                uint32_t addr = su32(&sA[buf][wm * 32 + (lane & 15)][ks + ((lane >> 4) << 3)]);
                LDSM_X4(a0[0], a0[1], a0[2], a0[3], addr);
                addr = su32(&sA[buf][wm * 32 + 16 + (lane & 15)][ks + ((lane >> 4) << 3)]);
                LDSM_X4(a1[0], a1[1], a1[2], a1[3], addr);
            }
            {
                const int bn = (lane & 7) + ((lane >> 4) << 3);
                const int bk = ks + (((lane >> 3) & 1) << 3);
                uint32_t addr = su32(&sB[buf][wn * 32 + bn][bk]);
                LDSM_X4(b[0], b[1], b[2], b[3], addr);
                addr = su32(&sB[buf][wn * 32 + 16 + bn][bk]);
                LDSM_X4(b[4], b[5], b[6], b[7], addr);
            }
#pragma unroll
            for (int ni = 0; ni < 4; ++ni) {
                MMA16816(acc[0][ni], a0, (&b[ni * 2]));
                MMA16816(acc[1][ni], a1, (&b[ni * 2]));
            }
        }
        if (it + 1 < TOT) sst(buf ^ 1);
        __syncthreads();
    }

    // epilogue: write C_part
    const int r  = lane >> 2;
    const int cc = (lane & 3) * 2;
#pragma unroll
    for (int mi = 0; mi < 2; ++mi)
#pragma unroll
        for (int ni = 0; ni < 4; ++ni) {
            const int row = wm * 32 + mi * 16 + r;
            const int col = n0 + wn * 32 + ni * 8 + cc;
            float2 v0 = make_float2(acc[mi][ni][0], acc[mi][ni][1]);
            float2 v1 = make_float2(acc[mi][ni][2], acc[mi][ni][3]);
            *reinterpret_cast<float2*>(&C[(size_t)row * N + col])       = v0;
            *reinterpret_cast<float2*>(&C[(size_t)(row + 8) * N + col]) = v1;
        }
}

// ---------------------------------------------------------------------------
// fp32 SIMT NT GEMM (used only for the two hoisted constant GEMMs)
// ---------------------------------------------------------------------------
template <bool TB>
__global__ __launch_bounds__(256)
void gemm128(const float* __restrict__ A, int lda,
             const float* __restrict__ Bm, int ldb,
             float* __restrict__ C, int N, int kchunk)
{
    __shared__ float As[16][128];
    __shared__ float Bs[16][68];

    const int tid = threadIdx.x;
    const int n0  = blockIdx.x * 64;
    const int k0  = blockIdx.y * kchunk;
    C += (size_t)blockIdx.y * 128 * N;

    const int my8 = (tid >> 4) * 8;
    const int nx4 = (tid & 15) * 4;
    const int am  = tid & 127;
    const int ak  = (tid >> 7) * 8;

    float acc[8][4];
#pragma unroll
    for (int i = 0; i < 8; ++i)
#pragma unroll
        for (int j = 0; j < 4; ++j) acc[i][j] = 0.0f;

    float4 pa[2];
    float4 pb;
    {
        const float* ap = A + (size_t)am * lda + k0 + ak;
        pa[0] = *reinterpret_cast<const float4*>(ap);
        pa[1] = *reinterpret_cast<const float4*>(ap + 4);
        pb = *reinterpret_cast<const float4*>(
            Bm + (size_t)(n0 + (tid >> 2)) * ldb + k0 + (tid & 3) * 4);
    }

    const int ntiles = kchunk / 16;
    for (int t = 0; t < ntiles; ++t) {
#pragma unroll
        for (int c = 0; c < 2; ++c) {
            As[ak + c * 4 + 0][am] = (&pa[c].x)[0];
            As[ak + c * 4 + 1][am] = (&pa[c].x)[1];
            As[ak + c * 4 + 2][am] = (&pa[c].x)[2];
            As[ak + c * 4 + 3][am] = (&pa[c].x)[3];
        }
        {
            const int nn = tid >> 2, cg4 = (tid & 3) * 4;
            Bs[cg4 + 0][nn] = pb.x;
            Bs[cg4 + 1][nn] = pb.y;
            Bs[cg4 + 2][nn] = pb.z;
            Bs[cg4 + 3][nn] = pb.w;
        }
        __syncthreads();

        if (t + 1 < ntiles) {
            const int kk0 = k0 + (t + 1) * 16;
            const float* ap = A + (size_t)am * lda + kk0 + ak;
            pa[0] = *reinterpret_cast<const float4*>(ap);
            pa[1] = *reinterpret_cast<const float4*>(ap + 4);
            pb = *reinterpret_cast<const float4*>(
                Bm + (size_t)(n0 + (tid >> 2)) * ldb + kk0 + (tid & 3) * 4);
        }

#pragma unroll
        for (int kk = 0; kk < 16; ++kk) {
            float av[8];
            *reinterpret_cast<float4*>(&av[0]) =
                *reinterpret_cast<const float4*>(&As[kk][my8]);
            *reinterpret_cast<float4*>(&av[4]) =
                *reinterpret_cast<const float4*>(&As[kk][my8 + 4]);
            float4 bq = *reinterpret_cast<const float4*>(&Bs[kk][nx4]);
            const float bv[4] = {bq.x, bq.y, bq.z, bq.w};
#pragma unroll
            for (int i = 0; i < 8; ++i)
#pragma unroll
                for (int j = 0; j < 4; ++j)
                    acc[i][j] += av[i] * bv[j];
        }
        __syncthreads();
    }

#pragma unroll
    for (int i = 0; i < 8; ++i) {
        float4 v = make_float4(acc[i][0], acc[i][1], acc[i][2], acc[i][3]);
        *reinterpret_cast<float4*>(C + (size_t)(my8 + i) * N + n0 + nx4) = v;
    }
}

// ---------------------------------------------------------------------------
// weight split: fp32 W [R,C] -> NT planes [R,C] x3 and NN planes [C,R] x3
// ---------------------------------------------------------------------------
__global__ void weight_split(const float* __restrict__ W, int R, int Cc,
                             size_t ntOff, size_t nnOff)
{
    __shared__ float tile[32][33];
    const int c0 = blockIdx.x * 32, r0 = blockIdx.y * 32;
    const int tx = threadIdx.x, ty = threadIdx.y;   // 32 x 8
    const size_t ps = (size_t)R * Cc;

#pragma unroll
    for (int i = 0; i < 4; ++i) {
        const int r = r0 + ty + i * 8, c = c0 + tx;
        const float a = W[(size_t)r * Cc + c];
        tile[ty + i * 8][tx] = a;
        __nv_bfloat16 h0, h1, h2;
        split3(a, h0, h1, h2);
        const size_t idx = (size_t)r * Cc + c;
        g_bpool[ntOff + idx]          = h0;
        g_bpool[ntOff + ps + idx]     = h1;
        g_bpool[ntOff + 2 * ps + idx] = h2;
    }
    __syncthreads();
#pragma unroll
    for (int i = 0; i < 4; ++i) {
        const int c = c0 + ty + i * 8, r = r0 + tx;
        const float a = tile[tx][ty + i * 8];
        __nv_bfloat16 h0, h1, h2;
        split3(a, h0, h1, h2);
        const size_t idx = (size_t)c * R + r;
        g_bpool[nnOff + idx]          = h0;
        g_bpool[nnOff + ps + idx]     = h1;
        g_bpool[nnOff + 2 * ps + idx] = h2;
    }
}

// ---------------------------------------------------------------------------
// collapse hoisted-constant GEMM partials (runs once)
// ---------------------------------------------------------------------------
__global__ void reduce_const_kernel()
{
    const size_t idx = (size_t)blockIdx.x * blockDim.x + threadIdx.x;
    float c0 = 0.0f;
#pragma unroll
    for (int p = 0; p < 8; ++p) c0 += g_pool[OFF_TI1 + (size_t)p * S1 + idx];
    g_pool[OFF_C0 + idx] = c0;
    float c1 = 0.0f;
#pragma unroll
    for (int p = 0; p < 4; ++p) c1 += g_pool[OFF_TI2 + (size_t)p * S1 + idx];
    g_pool[OFF_C1 + idx] = c1;
}

// ---------------------------------------------------------------------------
// LIF update; also emits bf16 spikes for phase-2 tensor GEMMs
// ---------------------------------------------------------------------------
__global__ void lif_kernel()
{
    const size_t idx = (size_t)blockIdx.x * blockDim.x + threadIdx.x;
    const int layer = blockIdx.y;

    float ti;
    size_t vo, spOff;
    if (layer == 0) {
        const float* t = g_pool + OFF_TI1;
        float s = 0.0f;
#pragma unroll
        for (int p = 0; p < PTI1; ++p) s += t[(size_t)p * S1 + idx];
        ti = s - g_pool[OFF_EG1 + idx] - g_pool[OFF_ED1 + idx];
        vo = OFF_V1; spOff = OFFB_SP1;
    } else {
        const float* t = g_pool + OFF_TI2;
        float s = 0.0f;
#pragma unroll
        for (int p = 0; p < PTI2; ++p) s += t[(size_t)p * S1 + idx];
        ti = s - g_pool[OFF_EG2 + idx] - g_pool[OFF_ED2 + idx];
        vo = OFF_V2; spOff = OFFB_SP2;
    }

    float j = g_pool[vo + 2 * S1 + idx];
    j = j + 0.1f * (ti - j);
    float v = g_pool[vo + idx];
    float r = g_pool[vo + 3 * S1 + idx];
    const bool refr = r > 0.0f;
    const float vn = v + 0.05f * (j - v);
    v = refr ? v : vn;
    const float s = (!refr && v > 1.0f) ? 1.0f : 0.0f;
    v = v * (1.0f - s);
    r = fmaxf(r - 1.0f, 0.0f);
    if (s != 0.0f) r = 2.0f;
    float tr = g_pool[vo + S1 + idx];
    tr = tr - tr * (1.0f / 20.0f) + s;

    g_pool[vo + idx]          = v;
    g_pool[vo + S1 + idx]     = tr;
    g_pool[vo + 2 * S1 + idx] = j;
    g_pool[vo + 3 * S1 + idx] = r;
    g_bpool[spOff + idx] = __float2bfloat16_rn(s);   // exact 0/1
}

// ---------------------------------------------------------------------------
// error recomputation; emits fp32 (for LIF subtraction / output) and
// split-bf16 planes for the phase-1 tensor GEMM A operands
// ---------------------------------------------------------------------------
__global__ void err_kernel(const float* __restrict__ x,
                           const float* __restrict__ y,
                           float* __restrict__ out)
{
    const size_t idx = (size_t)blockIdx.x * blockDim.x + threadIdx.x;
    const int n = (int)(idx & 4095);
    const int b = (int)(idx >> 12);

    const float tr1 = g_pool[OFF_TR1 + idx];
    const float tr2 = g_pool[OFF_TR2 + idx];

    float g2 = 0.0f;
#pragma unroll
    for (int p = 0; p < PG2; ++p) g2 += g_pool[OFF_G2 + (size_t)p * S1 + idx];
    const float eg1 = 0.5f * (tr1 - g2);
    g_pool[OFF_EG1 + idx] = eg1;
    {
        __nv_bfloat16 h0, h1, h2;
        split3(eg1, h0, h1, h2);
        g_bpool[OFFB_EG1S + idx]          = h0;
        g_bpool[OFFB_EG1S + S1 + idx]     = h1;
        g_bpool[OFFB_EG1S + 2 * S1 + idx] = h2;
    }

    float g3 = 0.0f;
#pragma unroll
    for (int p = 0; p < PG3; ++p) g3 += g_pool[OFF_G3 + (size_t)p * S1 + idx];
    const float ed2 = 0.5f * (tr2 - g3);
    g_pool[OFF_ED2 + idx] = ed2;
    {
        __nv_bfloat16 h0, h1, h2;
        split3(ed2, h0, h1, h2);
        g_bpool[OFFB_ED2S + idx]          = h0;
        g_bpool[OFFB_ED2S + S1 + idx]     = h1;
        g_bpool[OFFB_ED2S + 2 * S1 + idx] = h2;
    }

    g_pool[OFF_ED1 + idx] = 0.5f * (tr1 - g_pool[OFF_C0 + idx]);
    g_pool[OFF_EG2 + idx] = 0.5f * (tr2 - g_pool[OFF_C1 + idx]);

    if (n < DD0) {
        const size_t i0 = (size_t)b * DD0 + n;
        float zd = g_pool[OFF_ZD + i0];
        zd = zd - zd * 0.1f + x[i0];
        g_pool[OFF_ZD + i0] = zd;
        float g1 = 0.0f;
#pragma unroll
        for (int p = 0; p < PG1; ++p) g1 += g_pool[OFF_G1 + (size_t)p * S0 + i0];
        const float eg0 = 0.5f * (zd - g1);
        __nv_bfloat16 h0, h1, h2;
        split3(eg0, h0, h1, h2);
        g_bpool[OFFB_EG0S + i0]          = h0;
        g_bpool[OFFB_EG0S + S0 + i0]     = h1;
        g_bpool[OFFB_EG0S + 2 * S0 + i0] = h2;
    }
    if (n < DD3) {
        const size_t i3 = (size_t)b * DD3 + n;
        float zl = g_pool[OFF_ZL + i3];
        zl = zl - zl * 0.1f + y[i3];
        g_pool[OFF_ZL + i3] = zl;
        float g4 = 0.0f;
#pragma unroll
        for (int p = 0; p < PG4; ++p) g4 += g_pool[OFF_G4 + (size_t)p * S3 + i3];
        const float e = 0.5f * (zl - g4);
        g_pool[OFF_ED3 + i3] = e;
        __nv_bfloat16 h0, h1, h2;
        split3(e, h0, h1, h2);
        g_bpool[OFFB_ED3S + i3]          = h0;
        g_bpool[OFFB_ED3S + S3 + i3]     = h1;
        g_bpool[OFFB_ED3S + 2 * S3 + i3] = h2;
        if (out) out[i3] = e;
    }
}

// ---------------------------------------------------------------------------
// Host launcher (graph-capturable: kernel launches + async memsets only)
// ---------------------------------------------------------------------------
extern "C" void kernel_launch(void* const* d_in, const int* in_sizes, int n_in,
                              void* d_out, int out_size)
{
    const float* x  = (const float*)d_in[0];
    const float* y  = (const float*)d_in[1];
    const float* W0 = (const float*)d_in[2];
    const float* W1 = (const float*)d_in[3];
    const float* W2 = (const float*)d_in[4];
    const float* V0 = (const float*)d_in[5];
    const float* V1 = (const float*)d_in[6];
    const float* V2 = (const float*)d_in[7];
    float* out = (float*)d_out;
    (void)in_sizes; (void)n_in; (void)out_size;

    float* pool = nullptr;
    cudaGetSymbolAddress((void**)&pool, g_pool);
    __nv_bfloat16* bp = nullptr;
    cudaGetSymbolAddress((void**)&bp, g_bpool);

    // zero persistent fp32 state and bf16 activation-split planes
    cudaMemsetAsync(pool, 0, ZERO_FLOATS * sizeof(float), 0);
    cudaMemsetAsync(bp, 0, BZERO_ELEMS * sizeof(__nv_bfloat16), 0);

    // one-time weight splits (both layouts, 3 levels each)
    {
        dim3 blk(32, 8);
        weight_split<<<dim3(DD1 / 32, DD0 / 32), blk>>>(W0, DD0, DD1, OFFB_W0NT, OFFB_W0NN);
        weight_split<<<dim3(DD1 / 32, DD1 / 32), blk>>>(W1, DD1, DD1, OFFB_W1NT, OFFB_W1NN);
        weight_split<<<dim3(DD1 / 32, DD1 / 32), blk>>>(V1, DD1, DD1, OFFB_V1NT, OFFB_V1NN);
        weight_split<<<dim3(DD1 / 32, DD3 / 32), blk>>>(V2, DD3, DD1, OFFB_V2NT, OFFB_V2NN);
    }

    const unsigned EW_BLOCKS = (unsigned)(S1 / 256);

    // hoisted constant GEMMs (fp32 SIMT, once): C0 = x@V0^T, C1 = y@W2^T
    gemm128<true><<<dim3(DD1 / 64, 8), 256>>>(x, DD0, V0, DD0, pool + OFF_TI1, DD1, DD0 / 8);
    gemm128<true><<<dim3(DD1 / 64, 4), 256>>>(y, DD3, W2, DD3, pool + OFF_TI2, DD1, DD3 / 4);
    reduce_const_kernel<<<EW_BLOCKS, 256>>>();

    auto mma1 = [&](const __nv_bfloat16* A, size_t as, int K,
                    const __nv_bfloat16* B, size_t bs, float* C, int N, int sk) {
        gemm_mma<1><<<dim3((unsigned)(N / 64), (unsigned)sk), 256>>>(A, as, K, B, bs, C, N, K / sk);
    };
    auto mma2 = [&](const __nv_bfloat16* A, int K,
                    const __nv_bfloat16* B, size_t bs, float* C, int N, int sk) {
        gemm_mma<2><<<dim3((unsigned)(N / 64), (unsigned)sk), 256>>>(A, 0, K, B, bs, C, N, K / sk);
    };

    for (int step = 0; step < 16; ++step) {
        // phase 1: synaptic currents (6-term split-bf16, split-K partials)
        mma1(bp + OFFB_EG0S, S0, DD0, bp + OFFB_W0NN, szW0, pool + OFF_TI1,             DD1, PTI1A);
        mma1(bp + OFFB_ED2S, S1, DD1, bp + OFFB_V1NN, szV1, pool + OFF_TI1 + PTI1A * S1, DD1, PTI1B);
        mma1(bp + OFFB_EG1S, S1, DD1, bp + OFFB_W1NN, szW1, pool + OFF_TI2,             DD1, PTI2A);
        mma1(bp + OFFB_ED3S, S3, DD3, bp + OFFB_V2NN, szV2, pool + OFF_TI2 + PTI2A * S1, DD1, PTI2B);

        lif_kernel<<<dim3(EW_BLOCKS, 2), 256>>>();

        // phase 2: error-path GEMMs (exact: spike x 3 weight planes)
        mma2(bp + OFFB_SP1, DD1, bp + OFFB_W0NT, szW0, pool + OFF_G1, DD0, PG1);
        mma2(bp + OFFB_SP2, DD1, bp + OFFB_W1NT, szW1, pool + OFF_G2, DD1, PG2);
        mma2(bp + OFFB_SP1, DD1, bp + OFFB_V1NT, szV1, pool + OFF_G3, DD1, PG3);
        mma2(bp + OFFB_SP2, DD1, bp + OFFB_V2NT, szV2, pool + OFF_G4, DD3, PG4);

        err_kernel<<<EW_BLOCKS, 256>>>(x, y, step == 15 ? out : nullptr);
    }
}